// round 10
// baseline (speedup 1.0000x reference)
#include <cuda_runtime.h>
#include <math.h>
#include <stdint.h>

#define NN   50000
#define DEG  16
#define IND  128
#define EDIM 64
#define ODIM 128

// ---- scratch (device globals: allocation-free rule) ----
__device__ float g_A[NN * IND];             // h @ W1
__device__ float g_B[NN * IND];             // h @ W2
__device__ float g_agg[NN * 4 * IND];       // [mean|max|min|std]
// transposed + tf32-split weights (built once per launch by k_wprep)
__device__ float g_WT1h[IND * IND],  g_WT1l[IND * IND];   // [n][k]
__device__ float g_WT2h[IND * IND],  g_WT2l[IND * IND];
__device__ float g_WT3h[IND * EDIM], g_WT3l[IND * EDIM];  // edge W3^T [n][k]
__device__ float g_WTph[IND * 640],  g_WTpl[IND * 640];   // [n][k] k<128: Wp0; else folded Wsum

// ---- helpers ----
__device__ __forceinline__ float tf32r(float x) {
    uint32_t u; asm("cvt.rna.tf32.f32 %0, %1;" : "=r"(u) : "f"(x));
    return __uint_as_float(u);
}
__device__ __forceinline__ uint32_t smem_u32(const void* p) {
    uint32_t a; asm("{ .reg .u64 t; cvta.to.shared.u64 t, %1; cvt.u32.u64 %0, t; }" : "=r"(a) : "l"(p));
    return a;
}
__device__ __forceinline__ void cpa16(uint32_t dst, const void* src, bool valid) {
    int sz = valid ? 16 : 0;
    asm volatile("cp.async.ca.shared.global [%0], [%1], 16, %2;" :: "r"(dst), "l"(src), "r"(sz) : "memory");
}
#define CP_COMMIT() asm volatile("cp.async.commit_group;" ::: "memory")
#define CP_WAIT(n)  asm volatile("cp.async.wait_group %0;" :: "n"(n) : "memory")

__device__ __forceinline__ void mma8(float* c, uint32_t a0, uint32_t a1, uint32_t a2, uint32_t a3,
                                     uint32_t b0, uint32_t b1) {
    asm volatile(
        "mma.sync.aligned.m16n8k8.row.col.f32.tf32.tf32.f32 "
        "{%0,%1,%2,%3}, {%4,%5,%6,%7}, {%8,%9}, {%0,%1,%2,%3};"
        : "+f"(c[0]), "+f"(c[1]), "+f"(c[2]), "+f"(c[3])
        : "r"(a0), "r"(a1), "r"(a2), "r"(a3), "r"(b0), "r"(b1));
}

#define AST 36                       // smem row stride in floats (32 + 4 pad) -> conflict-free frags
#define ST_BYTES (128 * AST * 4)     // 18432 per 128x32 tile
// k_gemm stage layout: stage s at s*55296: [Araw | Bh | Bl]
#define SM_GEMM_TOT (2 * 3 * ST_BYTES)   // 110592

// ============================================================
// K0: build transposed tf32-split weights; fold Wsum (deg == 16 -> scalers == 1)
// ============================================================
__global__ void k_wprep(const float* __restrict__ Wpre, const float* __restrict__ Wpost) {
    int i = blockIdx.x * blockDim.x + threadIdx.x;
    if (i < IND * IND) {
        int n = i >> 7, k = i & 127;
        float w1 = Wpre[k * IND + n];
        float w2 = Wpre[IND * IND + k * IND + n];
        float h1 = tf32r(w1), h2 = tf32r(w2);
        g_WT1h[n * IND + k] = h1; g_WT1l[n * IND + k] = tf32r(w1 - h1);
        g_WT2h[n * IND + k] = h2; g_WT2l[n * IND + k] = tf32r(w2 - h2);
    }
    if (i < IND * EDIM) {
        int n = i & 127, k = i >> 7;
        float w3 = Wpre[2 * IND * IND + k * IND + n];
        float h3 = tf32r(w3);
        g_WT3h[n * EDIM + k] = h3; g_WT3l[n * EDIM + k] = tf32r(w3 - h3);
    }
    if (i < IND * 640) {
        int n = i / 640, k = i % 640;
        float w;
        if (k < IND) w = Wpost[k * ODIM + n];
        else {
            int r = k - IND;
            w = Wpost[(IND + r) * ODIM + n] + Wpost[(5 * IND + r) * ODIM + n]
              + Wpost[(9 * IND + r) * ODIM + n];
        }
        float hh = tf32r(w);
        g_WTph[(size_t)n * 640 + k] = hh;
        g_WTpl[(size_t)n * 640 + k] = tf32r(w - hh);
    }
}

// ============================================================
// shared mma inner step: one K-chunk (32) against staged [Araw|Bh|Bl]
// A split hi/lo at fragment-load time (cvt on idle fma/alu pipes).
// ============================================================
__device__ __forceinline__ void mma_chunk(const float* Araw, const float* Bh, const float* Bl,
                                          int warp_m, int warp_n, int g, int t4,
                                          float acc[2][8][4]) {
    #pragma unroll
    for (int k0 = 0; k0 < 32; k0 += 8) {
        uint32_t ah[2][4], al[2][4];
        #pragma unroll
        for (int mt = 0; mt < 2; mt++) {
            int r0 = warp_m * 32 + mt * 16 + g;
            float a0 = Araw[r0 * AST + k0 + t4];
            float a1 = Araw[(r0 + 8) * AST + k0 + t4];
            float a2 = Araw[r0 * AST + k0 + t4 + 4];
            float a3 = Araw[(r0 + 8) * AST + k0 + t4 + 4];
            float h0 = tf32r(a0), h1 = tf32r(a1), h2 = tf32r(a2), h3 = tf32r(a3);
            ah[mt][0] = __float_as_uint(h0); ah[mt][1] = __float_as_uint(h1);
            ah[mt][2] = __float_as_uint(h2); ah[mt][3] = __float_as_uint(h3);
            al[mt][0] = __float_as_uint(tf32r(a0 - h0));
            al[mt][1] = __float_as_uint(tf32r(a1 - h1));
            al[mt][2] = __float_as_uint(tf32r(a2 - h2));
            al[mt][3] = __float_as_uint(tf32r(a3 - h3));
        }
        #pragma unroll
        for (int nt = 0; nt < 8; nt++) {
            int n = warp_n * 64 + nt * 8 + g;
            uint32_t bh0 = __float_as_uint(Bh[n * AST + k0 + t4]);
            uint32_t bh1 = __float_as_uint(Bh[n * AST + k0 + t4 + 4]);
            uint32_t bl0 = __float_as_uint(Bl[n * AST + k0 + t4]);
            uint32_t bl1 = __float_as_uint(Bl[n * AST + k0 + t4 + 4]);
            #pragma unroll
            for (int mt = 0; mt < 2; mt++) {
                mma8(acc[mt][nt], ah[mt][0], ah[mt][1], ah[mt][2], ah[mt][3], bh0, bh1);
                mma8(acc[mt][nt], al[mt][0], al[mt][1], al[mt][2], al[mt][3], bh0, bh1);
                mma8(acc[mt][nt], ah[mt][0], ah[mt][1], ah[mt][2], ah[mt][3], bl0, bl1);
            }
        }
    }
}

// ============================================================
// K1/K3: cp.async double-buffered tf32 GEMM (3x split).
// sel: 0 -> g_A = h@W1; 1 -> g_B = h@W2; 2 -> out = [h|agg]@WTp^T + bias;
// sel 3: blockIdx.y picks 0/1.
// ============================================================
__global__ __launch_bounds__(256, 2) void k_gemm_mma(const float* __restrict__ X0,
                                                     const float* __restrict__ bias_in,
                                                     float* __restrict__ out_in,
                                                     int sel) {
    extern __shared__ float sm[];
    const uint32_t smb = smem_u32(sm);

    if (sel == 3) sel = blockIdx.y;
    const float *BTh, *BTl, *bias = nullptr;
    float* outp;
    int Ktot;
    if (sel == 0)      { BTh = g_WT1h; BTl = g_WT1l; outp = g_A;    Ktot = 128; }
    else if (sel == 1) { BTh = g_WT2h; BTl = g_WT2l; outp = g_B;    Ktot = 128; }
    else               { BTh = g_WTph; BTl = g_WTpl; outp = out_in; Ktot = 640; bias = bias_in; }
    const int NCH = Ktot / 32;

    const int tid = threadIdx.x;
    const int wid = tid >> 5, lane = tid & 31;
    const int g = lane >> 2, t4 = lane & 3;
    const int warp_m = wid & 3, warp_n = wid >> 2;
    const int m0 = blockIdx.x * 128;

    // staging coordinates (1024 float4s per 128x32 tile; 4 per thread)
    const int srow = tid >> 1;                // 0..127 (2 threads/row)
    const int sq0  = (tid & 1) * 4;           // q = sq0..sq0+3

    float acc[2][8][4];
    #pragma unroll
    for (int mt = 0; mt < 2; mt++)
        #pragma unroll
        for (int nt = 0; nt < 8; nt++)
            #pragma unroll
            for (int q = 0; q < 4; q++) acc[mt][nt][q] = 0.f;

    // stage-issue lambda (A raw + B hi/lo for chunk c into stage s)
    auto issue = [&](int c, int s) {
        uint32_t base = smb + s * (3 * ST_BYTES);
        int m = m0 + srow;
        bool mv = (m < NN);
        const float* ap;
        if (sel != 2 || c < 4) ap = X0 + (size_t)m * IND + c * 32;
        else                   ap = g_agg + (size_t)m * 4 * IND + (c - 4) * 32;
        #pragma unroll
        for (int q = sq0; q < sq0 + 4; q++)
            cpa16(base + srow * 144 + q * 16, ap + q * 4, mv);
        const float* bhp = BTh + (size_t)srow * Ktot + c * 32;
        const float* blp = BTl + (size_t)srow * Ktot + c * 32;
        #pragma unroll
        for (int q = sq0; q < sq0 + 4; q++) {
            cpa16(base + ST_BYTES + srow * 144 + q * 16, bhp + q * 4, true);
            cpa16(base + 2 * ST_BYTES + srow * 144 + q * 16, blp + q * 4, true);
        }
        CP_COMMIT();
    };

    issue(0, 0);
    for (int c = 0; c < NCH; c++) {
        if (c + 1 < NCH) issue(c + 1, (c + 1) & 1);
        if (c + 1 < NCH) { CP_WAIT(1); } else { CP_WAIT(0); }
        __syncthreads();
        const float* base = sm + (c & 1) * (3 * ST_BYTES / 4);
        mma_chunk(base, base + ST_BYTES / 4, base + 2 * ST_BYTES / 4,
                  warp_m, warp_n, g, t4, acc);
        __syncthreads();
    }

    // ---- epilogue ----
    #pragma unroll
    for (int mt = 0; mt < 2; mt++) {
        int r0 = m0 + warp_m * 32 + mt * 16 + g;
        #pragma unroll
        for (int nt = 0; nt < 8; nt++) {
            int col = warp_n * 64 + nt * 8 + t4 * 2;
            float b0 = 0.f, b1 = 0.f;
            if (bias) { b0 = bias[col]; b1 = bias[col + 1]; }
            if (r0 < NN) {
                float2 u = {acc[mt][nt][0] + b0, acc[mt][nt][1] + b1};
                *(float2*)(outp + (size_t)r0 * 128 + col) = u;
            }
            if (r0 + 8 < NN) {
                float2 u = {acc[mt][nt][2] + b0, acc[mt][nt][3] + b1};
                *(float2*)(outp + (size_t)(r0 + 8) * 128 + col) = u;
            }
        }
    }
}

// ============================================================
// K2: edge GEMM (ef@W3 tf32 3-split) fused with 4-aggregator reduce.
// CTA = 128 edges = exactly 8 nodes. ALL staging cp.async upfront
// (ef raw 2 chunks + W3 hi/lo 2 chunks), single wait, mma, reduce.
// ============================================================
#define ES_STRIDE 132
// layout: EF[c] at c*ST, W3h[c] at (2+c)*ST, W3l[c] at (4+c)*ST  -> 6*ST = 110592
__global__ __launch_bounds__(256, 2) void k_edge_mma(const float* __restrict__ ef,
                                                     const int* __restrict__ src,
                                                     const float* __restrict__ bpre) {
    extern __shared__ float sm[];
    const uint32_t smb = smem_u32(sm);
    float* Es = sm;                      // overlay after mma: [128][132]

    const int tid = threadIdx.x;
    const int wid = tid >> 5, lane = tid & 31;
    const int g = lane >> 2, t4 = lane & 3;
    const int warp_m = wid & 3, warp_n = wid >> 2;
    const size_t m0 = (size_t)blockIdx.x * 128;

    const int srow = tid >> 1;
    const int sq0  = (tid & 1) * 4;

    // hoist phase-2 scalars before staging
    const int n_node = blockIdx.x * 8 + wid;
    int sreg[DEG];
    {
        const int* srcp = src + n_node * DEG;
        #pragma unroll
        for (int j = 0; j < DEG; j++) sreg[j] = srcp[j];
    }

    // ---- stage everything asynchronously ----
    #pragma unroll
    for (int c = 0; c < 2; c++) {
        const float* ap = ef + (m0 + srow) * EDIM + c * 32;
        #pragma unroll
        for (int q = sq0; q < sq0 + 4; q++)
            cpa16(smb + c * ST_BYTES + srow * 144 + q * 16, ap + q * 4, true);
        const float* bhp = g_WT3h + (size_t)srow * EDIM + c * 32;
        const float* blp = g_WT3l + (size_t)srow * EDIM + c * 32;
        #pragma unroll
        for (int q = sq0; q < sq0 + 4; q++) {
            cpa16(smb + (2 + c) * ST_BYTES + srow * 144 + q * 16, bhp + q * 4, true);
            cpa16(smb + (4 + c) * ST_BYTES + srow * 144 + q * 16, blp + q * 4, true);
        }
    }
    CP_COMMIT();

    float acc[2][8][4];
    #pragma unroll
    for (int mt = 0; mt < 2; mt++)
        #pragma unroll
        for (int nt = 0; nt < 8; nt++)
            #pragma unroll
            for (int q = 0; q < 4; q++) acc[mt][nt][q] = 0.f;

    CP_WAIT(0);
    __syncthreads();

    #pragma unroll
    for (int c = 0; c < 2; c++)
        mma_chunk(sm + c * (ST_BYTES / 4), sm + (2 + c) * (ST_BYTES / 4), sm + (4 + c) * (ST_BYTES / 4),
                  warp_m, warp_n, g, t4, acc);

    __syncthreads();   // all mma reads done before Es overlays EF/W3h

    // ---- spill e tile to smem ----
    #pragma unroll
    for (int mt = 0; mt < 2; mt++) {
        int r0 = warp_m * 32 + mt * 16 + g;
        #pragma unroll
        for (int nt = 0; nt < 8; nt++) {
            int col = warp_n * 64 + nt * 8 + t4 * 2;
            *(float2*)&Es[r0 * ES_STRIDE + col]       = *(float2*)&acc[mt][nt][0];
            *(float2*)&Es[(r0 + 8) * ES_STRIDE + col] = *(float2*)&acc[mt][nt][2];
        }
    }
    __syncthreads();

    // ---- phase 2: warp w reduces node w; lane owns 4 cols ----
    {
        const int c0 = lane * 4;
        float4 Bb = *(const float4*)&g_B[(size_t)n_node * IND + c0];
        float4 bp = *(const float4*)&bpre[c0];
        Bb.x += bp.x; Bb.y += bp.y; Bb.z += bp.z; Bb.w += bp.w;

        float4 s1 = {0.f, 0.f, 0.f, 0.f}, s2 = {0.f, 0.f, 0.f, 0.f};
        float4 mx = {-3.4e38f, -3.4e38f, -3.4e38f, -3.4e38f};
        float4 mn = {3.4e38f, 3.4e38f, 3.4e38f, 3.4e38f};

        #pragma unroll
        for (int j = 0; j < DEG; j++) {
            float4 ev = *(const float4*)&Es[(wid * 16 + j) * ES_STRIDE + c0];
            float4 av = *(const float4*)&g_A[(size_t)sreg[j] * IND + c0];
            float4 e;
            e.x = ev.x + av.x + Bb.x; e.y = ev.y + av.y + Bb.y;
            e.z = ev.z + av.z + Bb.z; e.w = ev.w + av.w + Bb.w;
            s1.x += e.x; s1.y += e.y; s1.z += e.z; s1.w += e.w;
            s2.x += e.x * e.x; s2.y += e.y * e.y; s2.z += e.z * e.z; s2.w += e.w * e.w;
            mx.x = fmaxf(mx.x, e.x); mx.y = fmaxf(mx.y, e.y);
            mx.z = fmaxf(mx.z, e.z); mx.w = fmaxf(mx.w, e.w);
            mn.x = fminf(mn.x, e.x); mn.y = fminf(mn.y, e.y);
            mn.z = fminf(mn.z, e.z); mn.w = fminf(mn.w, e.w);
        }

        const float inv = 1.0f / (float)DEG;
        float4 me = {s1.x * inv, s1.y * inv, s1.z * inv, s1.w * inv};
        float4 sd;
        sd.x = sqrtf(fmaxf(s2.x * inv - me.x * me.x, 0.f) + 1e-5f);
        sd.y = sqrtf(fmaxf(s2.y * inv - me.y * me.y, 0.f) + 1e-5f);
        sd.z = sqrtf(fmaxf(s2.z * inv - me.z * me.z, 0.f) + 1e-5f);
        sd.w = sqrtf(fmaxf(s2.w * inv - me.w * me.w, 0.f) + 1e-5f);

        float* aggp = g_agg + (size_t)n_node * (4 * IND);
        *(float4*)&aggp[c0]            = me;
        *(float4*)&aggp[IND + c0]      = mx;
        *(float4*)&aggp[2 * IND + c0]  = mn;
        *(float4*)&aggp[3 * IND + c0]  = sd;
    }
}

// ============================================================
extern "C" void kernel_launch(void* const* d_in, const int* in_sizes, int n_in,
                              void* d_out, int out_size) {
    const float* h     = (const float*)d_in[0];
    const float* ef    = (const float*)d_in[1];
    const int*   src   = (const int*)d_in[2];
    // d_in[3] = dst: implicit (dst[e] = e/16), unused
    const float* Wpre  = (const float*)d_in[4];
    const float* bpre  = (const float*)d_in[5];
    const float* Wpost = (const float*)d_in[6];
    const float* bpost = (const float*)d_in[7];
    float* out = (float*)d_out;

    static bool attr_done = false;
    if (!attr_done) {
        cudaFuncSetAttribute(k_gemm_mma, cudaFuncAttributeMaxDynamicSharedMemorySize, SM_GEMM_TOT);
        cudaFuncSetAttribute(k_edge_mma, cudaFuncAttributeMaxDynamicSharedMemorySize, SM_GEMM_TOT);
        attr_done = true;
    }

    const int mblocks = (NN + 127) / 128;   // 391
    k_wprep<<<(IND * 640 + 255) / 256, 256>>>(Wpre, Wpost);
    dim3 gab(mblocks, 2);
    k_gemm_mma<<<gab, 256, SM_GEMM_TOT>>>(h, nullptr, nullptr, 3);     // g_A, g_B
    k_edge_mma<<<NN * DEG / 128, 256, SM_GEMM_TOT>>>(ef, src, bpre);   // g_agg
    k_gemm_mma<<<mblocks, 256, SM_GEMM_TOT>>>(h, bpost, out, 2);       // out
}

// round 13
// speedup vs baseline: 1.4009x; 1.4009x over previous
#include <cuda_runtime.h>
#include <math.h>
#include <stdint.h>

#define NN   50000
#define DEG  16
#define IND  128
#define EDIM 64
#define ODIM 128

// ---- scratch (device globals; bf16 data stored as uint32 PAIRS lo=even k) ----
__device__ float    g_A[NN * IND];            // h @ W1 (fp32)
__device__ float    g_B[NN * IND];            // h @ W2 (fp32)
__device__ uint32_t g_hH[NN * 64],   g_hL[NN * 64];     // h bf16 hi/lo pairs [m][64]
__device__ uint32_t g_aggH[NN * 256], g_aggL[NN * 256]; // agg bf16 pairs [m][256]
__device__ uint32_t g_W1H[IND * 64],  g_W1L[IND * 64];  // W^T [n][kpairs]
__device__ uint32_t g_W2H[IND * 64],  g_W2L[IND * 64];
__device__ uint32_t g_W3H[IND * 32],  g_W3L[IND * 32];
__device__ uint32_t g_WpH[IND * 320], g_WpL[IND * 320]; // k<64p: Wp0 ; else folded Wsum

// ---- helpers ----
__device__ __forceinline__ uint32_t pack_bf16x2(float lo, float hi) {
    uint32_t r; asm("cvt.rn.bf16x2.f32 %0, %1, %2;" : "=r"(r) : "f"(hi), "f"(lo)); return r;
}
__device__ __forceinline__ float bf_lo(uint32_t p) { return __uint_as_float(p << 16); }
__device__ __forceinline__ float bf_hi(uint32_t p) { return __uint_as_float(p & 0xffff0000u); }
__device__ __forceinline__ uint32_t smem_u32(const void* p) {
    uint32_t a; asm("{ .reg .u64 t; cvta.to.shared.u64 t, %1; cvt.u32.u64 %0, t; }" : "=r"(a) : "l"(p));
    return a;
}
__device__ __forceinline__ void cpa16(uint32_t dst, const void* src, bool valid) {
    int sz = valid ? 16 : 0;
    asm volatile("cp.async.ca.shared.global [%0], [%1], 16, %2;" :: "r"(dst), "l"(src), "r"(sz) : "memory");
}
#define CP_COMMIT() asm volatile("cp.async.commit_group;" ::: "memory")
#define CP_WAIT0()  asm volatile("cp.async.wait_group 0;" ::: "memory")

__device__ __forceinline__ void mma16(float* c, const uint32_t* a, uint32_t b0, uint32_t b1) {
    asm volatile(
        "mma.sync.aligned.m16n8k16.row.col.f32.bf16.bf16.f32 "
        "{%0,%1,%2,%3}, {%4,%5,%6,%7}, {%8,%9}, {%0,%1,%2,%3};"
        : "+f"(c[0]), "+f"(c[1]), "+f"(c[2]), "+f"(c[3])
        : "r"(a[0]), "r"(a[1]), "r"(a[2]), "r"(a[3]), "r"(b0), "r"(b1));
}

// smem tile: 128 rows x 16 words(k-pairs), row stride 20 words -> conflict-free frags
#define TILEW 2560                    // 128*20 words
#define STAGEW (4 * TILEW)            // Ah|Al|Bh|Bl
#define SM_GEMM_TOT (2 * STAGEW * 4)  // 81920 B
// edge: K=64 -> 32 words/row, stride 36
#define ETW 4608                      // 128*36
#define EFRAW_W (4 * ETW)             // float words base of raw ef (stride 68)
#define SM_EDGE_TOT ((4 * ETW + 128 * 68) * 4)   // 108544 B
#define ES_STRIDE 132

// ============================================================
// P0: h -> bf16 hi/lo pairs
// ============================================================
__global__ void k_prep_h(const float* __restrict__ h) {
    int i = blockIdx.x * blockDim.x + threadIdx.x;   // per float4
    if (i < NN * IND / 4) {
        float4 v = ((const float4*)h)[i];
        uint32_t h0 = pack_bf16x2(v.x, v.y), h1 = pack_bf16x2(v.z, v.w);
        uint32_t l0 = pack_bf16x2(v.x - bf_lo(h0), v.y - bf_hi(h0));
        uint32_t l1 = pack_bf16x2(v.z - bf_lo(h1), v.w - bf_hi(h1));
        ((uint2*)g_hH)[i] = make_uint2(h0, h1);
        ((uint2*)g_hL)[i] = make_uint2(l0, l1);
    }
}

// ============================================================
// P1: transposed bf16-split weights; fold Wsum (deg==16 -> scalers==1)
// ============================================================
__global__ void k_wprep(const float* __restrict__ Wpre, const float* __restrict__ Wpost) {
    int i = blockIdx.x * blockDim.x + threadIdx.x;
    if (i < IND * 64) {            // W1 / W2 pairs
        int n = i >> 6, p = i & 63, k = 2 * p;
        float a = Wpre[k * IND + n],       b = Wpre[(k + 1) * IND + n];
        uint32_t hw = pack_bf16x2(a, b);
        g_W1H[n * 64 + p] = hw;
        g_W1L[n * 64 + p] = pack_bf16x2(a - bf_lo(hw), b - bf_hi(hw));
        a = Wpre[IND * IND + k * IND + n]; b = Wpre[IND * IND + (k + 1) * IND + n];
        hw = pack_bf16x2(a, b);
        g_W2H[n * 64 + p] = hw;
        g_W2L[n * 64 + p] = pack_bf16x2(a - bf_lo(hw), b - bf_hi(hw));
    }
    if (i < IND * 32) {            // W3 pairs
        int n = i >> 5, p = i & 31, k = 2 * p;
        float a = Wpre[2 * IND * IND + k * IND + n], b = Wpre[2 * IND * IND + (k + 1) * IND + n];
        uint32_t hw = pack_bf16x2(a, b);
        g_W3H[n * 32 + p] = hw;
        g_W3L[n * 32 + p] = pack_bf16x2(a - bf_lo(hw), b - bf_hi(hw));
    }
    if (i < IND * 320) {           // Wpost pairs (k<128: Wp0; else folded Wsum)
        int n = i / 320, p = i % 320, k = 2 * p;
        float a, b;
        if (k < IND) { a = Wpost[k * ODIM + n]; b = Wpost[(k + 1) * ODIM + n]; }
        else {
            int r = k - IND;
            a = Wpost[(IND + r) * ODIM + n] + Wpost[(5 * IND + r) * ODIM + n] + Wpost[(9 * IND + r) * ODIM + n];
            r++;
            b = Wpost[(IND + r) * ODIM + n] + Wpost[(5 * IND + r) * ODIM + n] + Wpost[(9 * IND + r) * ODIM + n];
        }
        uint32_t hw = pack_bf16x2(a, b);
        g_WpH[(size_t)n * 320 + p] = hw;
        g_WpL[(size_t)n * 320 + p] = pack_bf16x2(a - bf_lo(hw), b - bf_hi(hw));
    }
}

// ============================================================
// mma inner: one K-chunk (32 = 2 k-steps of 16) from staged bf16 tiles
// ============================================================
__device__ __forceinline__ void mma_chunk(const uint32_t* Ah, const uint32_t* Al,
                                          const uint32_t* Bh, const uint32_t* Bl,
                                          int S, int woff,
                                          int warp_m, int warp_n, int g, int t4,
                                          float acc[2][8][4]) {
    #pragma unroll
    for (int ks = 0; ks < 2; ks++) {
        int wa = woff + ks * 8 + t4;
        uint32_t ah[2][4], al[2][4];
        #pragma unroll
        for (int mt = 0; mt < 2; mt++) {
            int r0 = warp_m * 32 + mt * 16 + g;
            ah[mt][0] = Ah[r0 * S + wa];     ah[mt][1] = Ah[(r0 + 8) * S + wa];
            ah[mt][2] = Ah[r0 * S + wa + 4]; ah[mt][3] = Ah[(r0 + 8) * S + wa + 4];
            al[mt][0] = Al[r0 * S + wa];     al[mt][1] = Al[(r0 + 8) * S + wa];
            al[mt][2] = Al[r0 * S + wa + 4]; al[mt][3] = Al[(r0 + 8) * S + wa + 4];
        }
        #pragma unroll
        for (int nt = 0; nt < 8; nt++) {
            int n = warp_n * 64 + nt * 8 + g;
            uint32_t bh0 = Bh[n * S + wa], bh1 = Bh[n * S + wa + 4];
            uint32_t bl0 = Bl[n * S + wa], bl1 = Bl[n * S + wa + 4];
            #pragma unroll
            for (int mt = 0; mt < 2; mt++) {
                mma16(acc[mt][nt], ah[mt], bh0, bh1);
                mma16(acc[mt][nt], al[mt], bh0, bh1);
                mma16(acc[mt][nt], ah[mt], bl0, bl1);
            }
        }
    }
}

// ============================================================
// K1/K3: all-cp.async double-buffered bf16 GEMM (3-split).
// sel 0/1: g_A/g_B = h@W1/W2 (K=128). sel 2: out = [h|agg]@Wp^T + bias (K=640).
// sel 3: blockIdx.y picks 0/1.
// ============================================================
__global__ __launch_bounds__(256, 2) void k_gemm(const float* __restrict__ bias_in,
                                                 float* __restrict__ out_in, int sel) {
    extern __shared__ uint32_t smw[];
    const uint32_t smb = smem_u32(smw);

    if (sel == 3) sel = blockIdx.y;
    const uint32_t *BH, *BL;
    float* outp; const float* bias = nullptr;
    int KP;   // k-pairs total
    if (sel == 0)      { BH = g_W1H; BL = g_W1L; outp = g_A;    KP = 64; }
    else if (sel == 1) { BH = g_W2H; BL = g_W2L; outp = g_B;    KP = 64; }
    else               { BH = g_WpH; BL = g_WpL; outp = out_in; KP = 320; bias = bias_in; }
    const int NCH = KP / 16;

    const int tid = threadIdx.x;
    const int wid = tid >> 5, lane = tid & 31;
    const int g = lane >> 2, t4 = lane & 3;
    const int warp_m = wid & 3, warp_n = wid >> 2;
    const int m0 = blockIdx.x * 128;
    const int row = tid >> 1, half = tid & 1;

    float acc[2][8][4];
    #pragma unroll
    for (int mt = 0; mt < 2; mt++)
        #pragma unroll
        for (int nt = 0; nt < 8; nt++)
            #pragma unroll
            for (int q = 0; q < 4; q++) acc[mt][nt][q] = 0.f;

    auto issue = [&](int c, int s) {
        uint32_t base = smb + s * STAGEW * 4;
        int m = m0 + row;
        bool mv = (m < NN);
        const uint32_t *ah, *alp;
        if (sel != 2 || c < 4) { ah = g_hH + (size_t)m * 64 + c * 16 + half * 8;
                                 alp = g_hL + (size_t)m * 64 + c * 16 + half * 8; }
        else { ah = g_aggH + (size_t)m * 256 + (c - 4) * 16 + half * 8;
               alp = g_aggL + (size_t)m * 256 + (c - 4) * 16 + half * 8; }
        uint32_t dA = base + (row * 20 + half * 8) * 4;
        cpa16(dA, ah, mv);                 cpa16(dA + 16, ah + 4, mv);
        cpa16(dA + TILEW * 4, alp, mv);    cpa16(dA + TILEW * 4 + 16, alp + 4, mv);
        const uint32_t* bh = BH + (size_t)row * KP + c * 16 + half * 8;
        const uint32_t* bl = BL + (size_t)row * KP + c * 16 + half * 8;
        uint32_t dB = base + (2 * TILEW + row * 20 + half * 8) * 4;
        cpa16(dB, bh, true);               cpa16(dB + 16, bh + 4, true);
        cpa16(dB + TILEW * 4, bl, true);   cpa16(dB + TILEW * 4 + 16, bl + 4, true);
        CP_COMMIT();
    };

    issue(0, 0);
    CP_WAIT0();
    __syncthreads();

    for (int c = 0; c < NCH; c++) {
        if (c + 1 < NCH) issue(c + 1, (c + 1) & 1);
        const uint32_t* st = smw + (c & 1) * STAGEW;
        mma_chunk(st, st + TILEW, st + 2 * TILEW, st + 3 * TILEW,
                  20, 0, warp_m, warp_n, g, t4, acc);
        CP_WAIT0();
        __syncthreads();
    }

    #pragma unroll
    for (int mt = 0; mt < 2; mt++) {
        int r0 = m0 + warp_m * 32 + mt * 16 + g;
        #pragma unroll
        for (int nt = 0; nt < 8; nt++) {
            int col = warp_n * 64 + nt * 8 + t4 * 2;
            float b0 = 0.f, b1 = 0.f;
            if (bias) { b0 = bias[col]; b1 = bias[col + 1]; }
            if (r0 < NN) {
                float2 u = {acc[mt][nt][0] + b0, acc[mt][nt][1] + b1};
                *(float2*)(outp + (size_t)r0 * 128 + col) = u;
            }
            if (r0 + 8 < NN) {
                float2 u = {acc[mt][nt][2] + b0, acc[mt][nt][3] + b1};
                *(float2*)(outp + (size_t)(r0 + 8) * 128 + col) = u;
            }
        }
    }
}

// ============================================================
// K2: edge GEMM (ef@W3 bf16 3-split) fused with aggregator reduce.
// CTA = 128 edges = 8 nodes. cp.async raw ef + W3 tiles, one convert pass,
// 2 mma chunks, smem spill, per-warp node reduce -> bf16 agg.
// ============================================================
__global__ __launch_bounds__(256, 2) void k_edge(const float* __restrict__ ef,
                                                 const int* __restrict__ src,
                                                 const float* __restrict__ bpre) {
    extern __shared__ uint32_t smw[];
    const uint32_t smb = smem_u32(smw);
    float* EFraw = (float*)(smw + EFRAW_W);   // [128][68] floats
    float* Es = (float*)smw;                  // overlay after mma: [128][132]

    const int tid = threadIdx.x;
    const int wid = tid >> 5, lane = tid & 31;
    const int g = lane >> 2, t4 = lane & 3;
    const int warp_m = wid & 3, warp_n = wid >> 2;
    const size_t m0 = (size_t)blockIdx.x * 128;
    const int row = tid >> 1, half = tid & 1;

    const int n_node = blockIdx.x * 8 + wid;
    int sreg[DEG];
    {
        const int* srcp = src + n_node * DEG;
        #pragma unroll
        for (int j = 0; j < DEG; j++) sreg[j] = srcp[j];
    }

    // ---- cp.async: raw ef + W3 bf16 tiles ----
    {
        const float* ap = ef + (m0 + row) * EDIM + half * 32;
        uint32_t dE = smb + (EFRAW_W + row * 68 + half * 32) * 4;
        #pragma unroll
        for (int q = 0; q < 8; q++) cpa16(dE + q * 16, ap + q * 4, true);
        const uint32_t* bh = g_W3H + row * 32 + half * 16;
        const uint32_t* bl = g_W3L + row * 32 + half * 16;
        uint32_t dB = smb + (2 * ETW + row * 36 + half * 16) * 4;
        #pragma unroll
        for (int q = 0; q < 4; q++) {
            cpa16(dB + q * 16, bh + q * 4, true);
            cpa16(dB + ETW * 4 + q * 16, bl + q * 4, true);
        }
        CP_COMMIT();
    }
    CP_WAIT0();
    __syncthreads();

    // ---- convert ef -> bf16 hi/lo tiles ----
    {
        uint32_t* EFh = smw;
        uint32_t* EFl = smw + ETW;
        #pragma unroll
        for (int q = 0; q < 8; q++) {
            float4 v = *(const float4*)&EFraw[row * 68 + half * 32 + q * 4];
            uint32_t h0 = pack_bf16x2(v.x, v.y), h1 = pack_bf16x2(v.z, v.w);
            uint32_t l0 = pack_bf16x2(v.x - bf_lo(h0), v.y - bf_hi(h0));
            uint32_t l1 = pack_bf16x2(v.z - bf_lo(h1), v.w - bf_hi(h1));
            *(uint2*)&EFh[row * 36 + half * 16 + q * 2] = make_uint2(h0, h1);
            *(uint2*)&EFl[row * 36 + half * 16 + q * 2] = make_uint2(l0, l1);
        }
    }
    __syncthreads();

    float acc[2][8][4];
    #pragma unroll
    for (int mt = 0; mt < 2; mt++)
        #pragma unroll
        for (int nt = 0; nt < 8; nt++)
            #pragma unroll
            for (int q = 0; q < 4; q++) acc[mt][nt][q] = 0.f;

    #pragma unroll
    for (int c = 0; c < 2; c++)
        mma_chunk(smw, smw + ETW, smw + 2 * ETW, smw + 3 * ETW,
                  36, c * 16, warp_m, warp_n, g, t4, acc);
    __syncthreads();

    // ---- spill e tile ----
    #pragma unroll
    for (int mt = 0; mt < 2; mt++) {
        int r0 = warp_m * 32 + mt * 16 + g;
        #pragma unroll
        for (int nt = 0; nt < 8; nt++) {
            int col = warp_n * 64 + nt * 8 + t4 * 2;
            *(float2*)&Es[r0 * ES_STRIDE + col]       = *(float2*)&acc[mt][nt][0];
            *(float2*)&Es[(r0 + 8) * ES_STRIDE + col] = *(float2*)&acc[mt][nt][2];
        }
    }
    __syncthreads();

    // ---- phase 2: warp w reduces node w; lane owns 4 cols ----
    {
        const int c0 = lane * 4;
        float4 Bb = *(const float4*)&g_B[(size_t)n_node * IND + c0];
        float4 bp = *(const float4*)&bpre[c0];
        Bb.x += bp.x; Bb.y += bp.y; Bb.z += bp.z; Bb.w += bp.w;

        float4 s1 = {0.f, 0.f, 0.f, 0.f}, s2 = {0.f, 0.f, 0.f, 0.f};
        float4 mx = {-3.4e38f, -3.4e38f, -3.4e38f, -3.4e38f};
        float4 mn = {3.4e38f, 3.4e38f, 3.4e38f, 3.4e38f};

        #pragma unroll
        for (int j = 0; j < DEG; j++) {
            float4 ev = *(const float4*)&Es[(wid * 16 + j) * ES_STRIDE + c0];
            float4 av = *(const float4*)&g_A[(size_t)sreg[j] * IND + c0];
            float4 e;
            e.x = ev.x + av.x + Bb.x; e.y = ev.y + av.y + Bb.y;
            e.z = ev.z + av.z + Bb.z; e.w = ev.w + av.w + Bb.w;
            s1.x += e.x; s1.y += e.y; s1.z += e.z; s1.w += e.w;
            s2.x += e.x * e.x; s2.y += e.y * e.y; s2.z += e.z * e.z; s2.w += e.w * e.w;
            mx.x = fmaxf(mx.x, e.x); mx.y = fmaxf(mx.y, e.y);
            mx.z = fmaxf(mx.z, e.z); mx.w = fmaxf(mx.w, e.w);
            mn.x = fminf(mn.x, e.x); mn.y = fminf(mn.y, e.y);
            mn.z = fminf(mn.z, e.z); mn.w = fminf(mn.w, e.w);
        }

        const float inv = 1.0f / (float)DEG;
        float4 me = {s1.x * inv, s1.y * inv, s1.z * inv, s1.w * inv};
        float4 sd;
        sd.x = sqrtf(fmaxf(s2.x * inv - me.x * me.x, 0.f) + 1e-5f);
        sd.y = sqrtf(fmaxf(s2.y * inv - me.y * me.y, 0.f) + 1e-5f);
        sd.z = sqrtf(fmaxf(s2.z * inv - me.z * me.z, 0.f) + 1e-5f);
        sd.w = sqrtf(fmaxf(s2.w * inv - me.w * me.w, 0.f) + 1e-5f);

        // store agg as bf16 hi/lo pairs: [n][ stat*64 + lane*2 (+1) ] word index
        float4 st4[4] = {me, mx, mn, sd};
        #pragma unroll
        for (int s = 0; s < 4; s++) {
            float4 v = st4[s];
            uint32_t h0 = pack_bf16x2(v.x, v.y), h1 = pack_bf16x2(v.z, v.w);
            uint32_t l0 = pack_bf16x2(v.x - bf_lo(h0), v.y - bf_hi(h0));
            uint32_t l1 = pack_bf16x2(v.z - bf_lo(h1), v.w - bf_hi(h1));
            size_t w = (size_t)n_node * 256 + s * 64 + lane * 2;
            *(uint2*)&g_aggH[w] = make_uint2(h0, h1);
            *(uint2*)&g_aggL[w] = make_uint2(l0, l1);
        }
    }
}

// ============================================================
extern "C" void kernel_launch(void* const* d_in, const int* in_sizes, int n_in,
                              void* d_out, int out_size) {
    const float* h     = (const float*)d_in[0];
    const float* ef    = (const float*)d_in[1];
    const int*   src   = (const int*)d_in[2];
    // d_in[3] = dst: implicit (dst[e] = e/16), unused
    const float* Wpre  = (const float*)d_in[4];
    const float* bpre  = (const float*)d_in[5];
    const float* Wpost = (const float*)d_in[6];
    const float* bpost = (const float*)d_in[7];
    float* out = (float*)d_out;

    static bool attr_done = false;
    if (!attr_done) {
        cudaFuncSetAttribute(k_gemm, cudaFuncAttributeMaxDynamicSharedMemorySize, SM_GEMM_TOT);
        cudaFuncSetAttribute(k_edge, cudaFuncAttributeMaxDynamicSharedMemorySize, SM_EDGE_TOT);
        attr_done = true;
    }

    const int mblocks = (NN + 127) / 128;   // 391
    k_prep_h<<<(NN * IND / 4 + 255) / 256, 256>>>(h);
    k_wprep<<<(IND * 320 + 255) / 256, 256>>>(Wpre, Wpost);
    dim3 gab(mblocks, 2);
    k_gemm<<<gab, 256, SM_GEMM_TOT>>>(nullptr, nullptr, 3);       // g_A, g_B
    k_edge<<<NN * DEG / 128, 256, SM_EDGE_TOT>>>(ef, src, bpre);  // g_aggH/L
    k_gemm<<<mblocks, 256, SM_GEMM_TOT>>>(bpost, out, 2);         // out
}

// round 14
// speedup vs baseline: 1.6607x; 1.1854x over previous
#include <cuda_runtime.h>
#include <math.h>
#include <stdint.h>

#define NN   50000
#define DEG  16
#define IND  128
#define EDIM 64
#define ODIM 128

// ---- scratch (device globals; bf16 data stored as uint32 PAIRS lo=even k) ----
__device__ float    g_A[NN * IND];            // h @ W1 (fp32)
__device__ float    g_B[NN * IND];            // h @ W2 (fp32)
__device__ uint32_t g_hH[NN * 64],   g_hL[NN * 64];     // h bf16 hi/lo pairs [m][64]
__device__ uint32_t g_aggH[NN * 256], g_aggL[NN * 256]; // agg bf16 pairs [m][256]
__device__ uint32_t g_W1H[IND * 64],  g_W1L[IND * 64];  // W^T [n][kpairs]
__device__ uint32_t g_W2H[IND * 64],  g_W2L[IND * 64];
__device__ uint32_t g_W3H[IND * 32],  g_W3L[IND * 32];
__device__ uint32_t g_WpH[IND * 320], g_WpL[IND * 320]; // k<64p: Wp0 ; else folded Wsum

// ---- helpers ----
__device__ __forceinline__ uint32_t pack_bf16x2(float lo, float hi) {
    uint32_t r; asm("cvt.rn.bf16x2.f32 %0, %1, %2;" : "=r"(r) : "f"(hi), "f"(lo)); return r;
}
__device__ __forceinline__ float bf_lo(uint32_t p) { return __uint_as_float(p << 16); }
__device__ __forceinline__ float bf_hi(uint32_t p) { return __uint_as_float(p & 0xffff0000u); }
__device__ __forceinline__ uint32_t smem_u32(const void* p) {
    uint32_t a; asm("{ .reg .u64 t; cvta.to.shared.u64 t, %1; cvt.u32.u64 %0, t; }" : "=r"(a) : "l"(p));
    return a;
}
__device__ __forceinline__ void cpa16(uint32_t dst, const void* src, bool valid) {
    int sz = valid ? 16 : 0;
    asm volatile("cp.async.ca.shared.global [%0], [%1], 16, %2;" :: "r"(dst), "l"(src), "r"(sz) : "memory");
}
#define CP_COMMIT() asm volatile("cp.async.commit_group;" ::: "memory")
#define CP_WAIT0()  asm volatile("cp.async.wait_group 0;" ::: "memory")

__device__ __forceinline__ void mma16(float* c, const uint32_t* a, uint32_t b0, uint32_t b1) {
    asm volatile(
        "mma.sync.aligned.m16n8k16.row.col.f32.bf16.bf16.f32 "
        "{%0,%1,%2,%3}, {%4,%5,%6,%7}, {%8,%9}, {%0,%1,%2,%3};"
        : "+f"(c[0]), "+f"(c[1]), "+f"(c[2]), "+f"(c[3])
        : "r"(a[0]), "r"(a[1]), "r"(a[2]), "r"(a[3]), "r"(b0), "r"(b1));
}
__device__ __forceinline__ void ldsm4(uint32_t* r, uint32_t a) {
    asm volatile("ldmatrix.sync.aligned.m8n8.x4.shared.b16 {%0,%1,%2,%3}, [%4];"
        : "=r"(r[0]), "=r"(r[1]), "=r"(r[2]), "=r"(r[3]) : "r"(a));
}

// smem tile: 128 rows x 16 words(k-pairs), row stride 20 words (80B, 16B-aligned,
// conflict-free ldmatrix row rotation)
#define TILEW 2560                    // 128*20 words
#define STAGEW (4 * TILEW)            // Ah|Al|Bh|Bl
#define SM_GEMM_TOT (2 * STAGEW * 4)  // 81920 B
// edge: K=64 -> 32 words/row, stride 36 (144B rows)
#define ETW 4608                      // 128*36 words
#define SM_EDGE_TOT (4 * ETW * 4)     // 73728 B  (EFh|EFl|W3h|W3l; Es overlays EFh/EFl)
#define ES_STRIDE 132

// ============================================================
// P0: h -> bf16 hi/lo pairs
// ============================================================
__global__ void k_prep_h(const float* __restrict__ h) {
    int i = blockIdx.x * blockDim.x + threadIdx.x;   // per float4
    if (i < NN * IND / 4) {
        float4 v = ((const float4*)h)[i];
        uint32_t h0 = pack_bf16x2(v.x, v.y), h1 = pack_bf16x2(v.z, v.w);
        uint32_t l0 = pack_bf16x2(v.x - bf_lo(h0), v.y - bf_hi(h0));
        uint32_t l1 = pack_bf16x2(v.z - bf_lo(h1), v.w - bf_hi(h1));
        ((uint2*)g_hH)[i] = make_uint2(h0, h1);
        ((uint2*)g_hL)[i] = make_uint2(l0, l1);
    }
}

// ============================================================
// P1: transposed bf16-split weights; fold Wsum (deg==16 -> scalers==1)
// ============================================================
__global__ void k_wprep(const float* __restrict__ Wpre, const float* __restrict__ Wpost) {
    int i = blockIdx.x * blockDim.x + threadIdx.x;
    if (i < IND * 64) {            // W1 / W2 pairs
        int n = i >> 6, p = i & 63, k = 2 * p;
        float a = Wpre[k * IND + n],       b = Wpre[(k + 1) * IND + n];
        uint32_t hw = pack_bf16x2(a, b);
        g_W1H[n * 64 + p] = hw;
        g_W1L[n * 64 + p] = pack_bf16x2(a - bf_lo(hw), b - bf_hi(hw));
        a = Wpre[IND * IND + k * IND + n]; b = Wpre[IND * IND + (k + 1) * IND + n];
        hw = pack_bf16x2(a, b);
        g_W2H[n * 64 + p] = hw;
        g_W2L[n * 64 + p] = pack_bf16x2(a - bf_lo(hw), b - bf_hi(hw));
    }
    if (i < IND * 32) {            // W3 pairs
        int n = i >> 5, p = i & 31, k = 2 * p;
        float a = Wpre[2 * IND * IND + k * IND + n], b = Wpre[2 * IND * IND + (k + 1) * IND + n];
        uint32_t hw = pack_bf16x2(a, b);
        g_W3H[n * 32 + p] = hw;
        g_W3L[n * 32 + p] = pack_bf16x2(a - bf_lo(hw), b - bf_hi(hw));
    }
    if (i < IND * 320) {           // Wpost pairs (k<128: Wp0; else folded Wsum)
        int n = i / 320, p = i % 320, k = 2 * p;
        float a, b;
        if (k < IND) { a = Wpost[k * ODIM + n]; b = Wpost[(k + 1) * ODIM + n]; }
        else {
            int r = k - IND;
            a = Wpost[(IND + r) * ODIM + n] + Wpost[(5 * IND + r) * ODIM + n] + Wpost[(9 * IND + r) * ODIM + n];
            r++;
            b = Wpost[(IND + r) * ODIM + n] + Wpost[(5 * IND + r) * ODIM + n] + Wpost[(9 * IND + r) * ODIM + n];
        }
        uint32_t hw = pack_bf16x2(a, b);
        g_WpH[(size_t)n * 320 + p] = hw;
        g_WpL[(size_t)n * 320 + p] = pack_bf16x2(a - bf_lo(hw), b - bf_hi(hw));
    }
}

// ============================================================
// mma inner: one K-chunk (32 vals = 2 ksteps of 16) via ldmatrix.x4 frag loads.
// aAh/aAl/aBh/aBl: per-lane byte addresses (lane row/col + chunk offset folded in).
// SB = row stride in BYTES.
// ============================================================
template<int SB>
__device__ __forceinline__ void mma_chunk(uint32_t aAh, uint32_t aAl,
                                          uint32_t aBh, uint32_t aBl,
                                          float acc[2][8][4]) {
    #pragma unroll
    for (int ks = 0; ks < 2; ks++) {
        uint32_t ah[2][4], al[2][4];
        #pragma unroll
        for (int mt = 0; mt < 2; mt++) {
            ldsm4(ah[mt], aAh + mt * (16 * SB) + ks * 32);
            ldsm4(al[mt], aAl + mt * (16 * SB) + ks * 32);
        }
        #pragma unroll
        for (int ntp = 0; ntp < 4; ntp++) {
            uint32_t bh[4], bl[4];
            ldsm4(bh, aBh + ntp * (16 * SB) + ks * 32);
            ldsm4(bl, aBl + ntp * (16 * SB) + ks * 32);
            #pragma unroll
            for (int n2 = 0; n2 < 2; n2++) {
                int nt = ntp * 2 + n2;
                #pragma unroll
                for (int mt = 0; mt < 2; mt++) {
                    mma16(acc[mt][nt], ah[mt], bh[n2 * 2], bh[n2 * 2 + 1]);
                    mma16(acc[mt][nt], al[mt], bh[n2 * 2], bh[n2 * 2 + 1]);
                    mma16(acc[mt][nt], ah[mt], bl[n2 * 2], bl[n2 * 2 + 1]);
                }
            }
        }
    }
}

// per-lane ldmatrix address components (byte offsets within a tile)
struct LaneAddr { uint32_t a, b; };
__device__ __forceinline__ LaneAddr lane_addr(int lane, int warp_m, int warp_n, int SB) {
    int arow = lane & 15, ahalf = lane >> 4;
    int bidx = lane & 7, bq = lane >> 3;
    int brow = (bq >> 1) * 8 + bidx;
    int bcol = (bq & 1) * 16;       // bytes
    LaneAddr r;
    r.a = (warp_m * 32 + arow) * SB + ahalf * 16;
    r.b = (warp_n * 64 + brow) * SB + bcol;
    return r;
}

// ============================================================
// K1/K3: all-cp.async double-buffered bf16 GEMM (3-split) + ldmatrix frags.
// sel 0/1: g_A/g_B = h@W1/W2 (K=128). sel 2: out = [h|agg]@Wp^T + bias (K=640).
// sel 3: blockIdx.y picks 0/1.
// ============================================================
__global__ __launch_bounds__(256, 2) void k_gemm(const float* __restrict__ bias_in,
                                                 float* __restrict__ out_in, int sel) {
    extern __shared__ uint32_t smw[];
    const uint32_t smb = smem_u32(smw);

    if (sel == 3) sel = blockIdx.y;
    const uint32_t *BH, *BL;
    float* outp; const float* bias = nullptr;
    int KP;   // k-pairs total
    if (sel == 0)      { BH = g_W1H; BL = g_W1L; outp = g_A;    KP = 64; }
    else if (sel == 1) { BH = g_W2H; BL = g_W2L; outp = g_B;    KP = 64; }
    else               { BH = g_WpH; BL = g_WpL; outp = out_in; KP = 320; bias = bias_in; }
    const int NCH = KP / 16;

    const int tid = threadIdx.x;
    const int wid = tid >> 5, lane = tid & 31;
    const int g = lane >> 2, t4 = lane & 3;
    const int warp_m = wid & 3, warp_n = wid >> 2;
    const int m0 = blockIdx.x * 128;
    const int row = tid >> 1, half = tid & 1;
    const LaneAddr la = lane_addr(lane, warp_m, warp_n, 80);

    float acc[2][8][4];
    #pragma unroll
    for (int mt = 0; mt < 2; mt++)
        #pragma unroll
        for (int nt = 0; nt < 8; nt++)
            #pragma unroll
            for (int q = 0; q < 4; q++) acc[mt][nt][q] = 0.f;

    auto issue = [&](int c, int s) {
        uint32_t base = smb + s * STAGEW * 4;
        int m = m0 + row;
        bool mv = (m < NN);
        const uint32_t *ah, *alp;
        if (sel != 2 || c < 4) { ah = g_hH + (size_t)m * 64 + c * 16 + half * 8;
                                 alp = g_hL + (size_t)m * 64 + c * 16 + half * 8; }
        else { ah = g_aggH + (size_t)m * 256 + (c - 4) * 16 + half * 8;
               alp = g_aggL + (size_t)m * 256 + (c - 4) * 16 + half * 8; }
        uint32_t dA = base + (row * 20 + half * 8) * 4;
        cpa16(dA, ah, mv);                 cpa16(dA + 16, ah + 4, mv);
        cpa16(dA + TILEW * 4, alp, mv);    cpa16(dA + TILEW * 4 + 16, alp + 4, mv);
        const uint32_t* bh = BH + (size_t)row * KP + c * 16 + half * 8;
        const uint32_t* bl = BL + (size_t)row * KP + c * 16 + half * 8;
        uint32_t dB = base + (2 * TILEW + row * 20 + half * 8) * 4;
        cpa16(dB, bh, true);               cpa16(dB + 16, bh + 4, true);
        cpa16(dB + TILEW * 4, bl, true);   cpa16(dB + TILEW * 4 + 16, bl + 4, true);
        CP_COMMIT();
    };

    issue(0, 0);
    CP_WAIT0();
    __syncthreads();

    for (int c = 0; c < NCH; c++) {
        if (c + 1 < NCH) issue(c + 1, (c + 1) & 1);
        const uint32_t sb = smb + (c & 1) * STAGEW * 4;
        mma_chunk<80>(sb + la.a, sb + TILEW * 4 + la.a,
                      sb + 2 * TILEW * 4 + la.b, sb + 3 * TILEW * 4 + la.b, acc);
        CP_WAIT0();
        __syncthreads();
    }

    #pragma unroll
    for (int mt = 0; mt < 2; mt++) {
        int r0 = m0 + warp_m * 32 + mt * 16 + g;
        #pragma unroll
        for (int nt = 0; nt < 8; nt++) {
            int col = warp_n * 64 + nt * 8 + t4 * 2;
            float b0 = 0.f, b1 = 0.f;
            if (bias) { b0 = bias[col]; b1 = bias[col + 1]; }
            if (r0 < NN) {
                float2 u = {acc[mt][nt][0] + b0, acc[mt][nt][1] + b1};
                *(float2*)(outp + (size_t)r0 * 128 + col) = u;
            }
            if (r0 + 8 < NN) {
                float2 u = {acc[mt][nt][2] + b0, acc[mt][nt][3] + b1};
                *(float2*)(outp + (size_t)(r0 + 8) * 128 + col) = u;
            }
        }
    }
}

// ============================================================
// K2: edge GEMM (ef@W3 bf16 3-split) fused with aggregator reduce.
// CTA = 128 edges = 8 nodes. W3 via cp.async; ef via LDG->convert->STS
// (no raw smem round trip). ldmatrix frags, smem spill, per-warp node reduce.
// ============================================================
__global__ __launch_bounds__(256, 2) void k_edge(const float* __restrict__ ef,
                                                 const int* __restrict__ src,
                                                 const float* __restrict__ bpre) {
    extern __shared__ uint32_t smw[];
    const uint32_t smb = smem_u32(smw);
    float* Es = (float*)smw;                  // overlay after mma: [128][132] fp32

    const int tid = threadIdx.x;
    const int wid = tid >> 5, lane = tid & 31;
    const int g = lane >> 2, t4 = lane & 3;
    const int warp_m = wid & 3, warp_n = wid >> 2;
    const size_t m0 = (size_t)blockIdx.x * 128;
    const int row = tid >> 1, half = tid & 1;
    const LaneAddr la = lane_addr(lane, warp_m, warp_n, 144);

    const int n_node = blockIdx.x * 8 + wid;
    int sreg[DEG];
    {
        const int* srcp = src + n_node * DEG;
        #pragma unroll
        for (int j = 0; j < DEG; j++) sreg[j] = srcp[j];
    }

    // ---- cp.async W3 tiles first (L2 latency overlaps ef LDGs below) ----
    {
        const uint32_t* bh = g_W3H + row * 32 + half * 16;
        const uint32_t* bl = g_W3L + row * 32 + half * 16;
        uint32_t dB = smb + (2 * ETW + row * 36 + half * 16) * 4;
        #pragma unroll
        for (int q = 0; q < 4; q++) {
            cpa16(dB + q * 16, bh + q * 4, true);
            cpa16(dB + ETW * 4 + q * 16, bl + q * 4, true);
        }
        CP_COMMIT();
    }

    // ---- LDG ef -> convert in regs -> STS bf16 hi/lo tiles ----
    {
        const float4* ap = (const float4*)(ef + (m0 + row) * EDIM + half * 32);
        float4 v[8];
        #pragma unroll
        for (int q = 0; q < 8; q++) v[q] = ap[q];
        uint32_t* EFh = smw;
        uint32_t* EFl = smw + ETW;
        #pragma unroll
        for (int q = 0; q < 8; q++) {
            uint32_t h0 = pack_bf16x2(v[q].x, v[q].y), h1 = pack_bf16x2(v[q].z, v[q].w);
            uint32_t l0 = pack_bf16x2(v[q].x - bf_lo(h0), v[q].y - bf_hi(h0));
            uint32_t l1 = pack_bf16x2(v[q].z - bf_lo(h1), v[q].w - bf_hi(h1));
            *(uint2*)&EFh[row * 36 + half * 16 + q * 2] = make_uint2(h0, h1);
            *(uint2*)&EFl[row * 36 + half * 16 + q * 2] = make_uint2(l0, l1);
        }
    }
    CP_WAIT0();
    __syncthreads();

    float acc[2][8][4];
    #pragma unroll
    for (int mt = 0; mt < 2; mt++)
        #pragma unroll
        for (int nt = 0; nt < 8; nt++)
            #pragma unroll
            for (int q = 0; q < 4; q++) acc[mt][nt][q] = 0.f;

    #pragma unroll
    for (int c = 0; c < 2; c++)   // K=64: two 32-chunks at word offsets 0,16 (=64B)
        mma_chunk<144>(smb + la.a + c * 64, smb + ETW * 4 + la.a + c * 64,
                       smb + 2 * ETW * 4 + la.b + c * 64, smb + 3 * ETW * 4 + la.b + c * 64, acc);
    __syncthreads();   // all frag reads done before Es overlays EF tiles

    // ---- spill e tile (fp32) ----
    #pragma unroll
    for (int mt = 0; mt < 2; mt++) {
        int r0 = warp_m * 32 + mt * 16 + g;
        #pragma unroll
        for (int nt = 0; nt < 8; nt++) {
            int col = warp_n * 64 + nt * 8 + t4 * 2;
            *(float2*)&Es[r0 * ES_STRIDE + col]       = *(float2*)&acc[mt][nt][0];
            *(float2*)&Es[(r0 + 8) * ES_STRIDE + col] = *(float2*)&acc[mt][nt][2];
        }
    }
    __syncthreads();

    // ---- phase 2: warp w reduces node w; lane owns 4 cols ----
    {
        const int c0 = lane * 4;
        float4 Bb = *(const float4*)&g_B[(size_t)n_node * IND + c0];
        float4 bp = *(const float4*)&bpre[c0];
        Bb.x += bp.x; Bb.y += bp.y; Bb.z += bp.z; Bb.w += bp.w;

        float4 s1 = {0.f, 0.f, 0.f, 0.f}, s2 = {0.f, 0.f, 0.f, 0.f};
        float4 mx = {-3.4e38f, -3.4e38f, -3.4e38f, -3.4e38f};
        float4 mn = {3.4e38f, 3.4e38f, 3.4e38f, 3.4e38f};

        #pragma unroll
        for (int j = 0; j < DEG; j++) {
            float4 ev = *(const float4*)&Es[(wid * 16 + j) * ES_STRIDE + c0];
            float4 av = *(const float4*)&g_A[(size_t)sreg[j] * IND + c0];
            float4 e;
            e.x = ev.x + av.x + Bb.x; e.y = ev.y + av.y + Bb.y;
            e.z = ev.z + av.z + Bb.z; e.w = ev.w + av.w + Bb.w;
            s1.x += e.x; s1.y += e.y; s1.z += e.z; s1.w += e.w;
            s2.x += e.x * e.x; s2.y += e.y * e.y; s2.z += e.z * e.z; s2.w += e.w * e.w;
            mx.x = fmaxf(mx.x, e.x); mx.y = fmaxf(mx.y, e.y);
            mx.z = fmaxf(mx.z, e.z); mx.w = fmaxf(mx.w, e.w);
            mn.x = fminf(mn.x, e.x); mn.y = fminf(mn.y, e.y);
            mn.z = fminf(mn.z, e.z); mn.w = fminf(mn.w, e.w);
        }

        const float inv = 1.0f / (float)DEG;
        float4 me = {s1.x * inv, s1.y * inv, s1.z * inv, s1.w * inv};
        float4 sd;
        sd.x = sqrtf(fmaxf(s2.x * inv - me.x * me.x, 0.f) + 1e-5f);
        sd.y = sqrtf(fmaxf(s2.y * inv - me.y * me.y, 0.f) + 1e-5f);
        sd.z = sqrtf(fmaxf(s2.z * inv - me.z * me.z, 0.f) + 1e-5f);
        sd.w = sqrtf(fmaxf(s2.w * inv - me.w * me.w, 0.f) + 1e-5f);

        float4 st4[4] = {me, mx, mn, sd};
        #pragma unroll
        for (int s = 0; s < 4; s++) {
            float4 v = st4[s];
            uint32_t h0 = pack_bf16x2(v.x, v.y), h1 = pack_bf16x2(v.z, v.w);
            uint32_t l0 = pack_bf16x2(v.x - bf_lo(h0), v.y - bf_hi(h0));
            uint32_t l1 = pack_bf16x2(v.z - bf_lo(h1), v.w - bf_hi(h1));
            size_t w = (size_t)n_node * 256 + s * 64 + lane * 2;
            *(uint2*)&g_aggH[w] = make_uint2(h0, h1);
            *(uint2*)&g_aggL[w] = make_uint2(l0, l1);
        }
    }
}

// ============================================================
extern "C" void kernel_launch(void* const* d_in, const int* in_sizes, int n_in,
                              void* d_out, int out_size) {
    const float* h     = (const float*)d_in[0];
    const float* ef    = (const float*)d_in[1];
    const int*   src   = (const int*)d_in[2];
    // d_in[3] = dst: implicit (dst[e] = e/16), unused
    const float* Wpre  = (const float*)d_in[4];
    const float* bpre  = (const float*)d_in[5];
    const float* Wpost = (const float*)d_in[6];
    const float* bpost = (const float*)d_in[7];
    float* out = (float*)d_out;

    static bool attr_done = false;
    if (!attr_done) {
        cudaFuncSetAttribute(k_gemm, cudaFuncAttributeMaxDynamicSharedMemorySize, SM_GEMM_TOT);
        cudaFuncSetAttribute(k_edge, cudaFuncAttributeMaxDynamicSharedMemorySize, SM_EDGE_TOT);
        attr_done = true;
    }

    const int mblocks = (NN + 127) / 128;   // 391
    k_prep_h<<<(NN * IND / 4 + 255) / 256, 256>>>(h);
    k_wprep<<<(IND * 320 + 255) / 256, 256>>>(Wpre, Wpost);
    dim3 gab(mblocks, 2);
    k_gemm<<<gab, 256, SM_GEMM_TOT>>>(nullptr, nullptr, 3);       // g_A, g_B
    k_edge<<<NN * DEG / 128, 256, SM_EDGE_TOT>>>(ef, src, bpre);  // g_aggH/L
    k_gemm<<<mblocks, 256, SM_GEMM_TOT>>>(bpost, out, 2);         // out
}